// round 2
// baseline (speedup 1.0000x reference)
#include <cuda_runtime.h>

// PostProcessingBlock: 50 iterations of NOTEARS-style augmented-Lagrangian
// updates on 512 independent 64x64 matrices. One CTA (128 threads) per batch
// element; all state in shared memory. Matmuls use packed fp32x2 FFMA.

#define LDM   68                  // padded row stride (floats)
#define MATF  (64 * LDM)
#define NTH   128

typedef unsigned long long u64;

__device__ __forceinline__ u64 rep2(float v) {
    u64 r;
    asm("mov.b64 %0, {%1, %1};" : "=l"(r) : "r"(__float_as_uint(v)));
    return r;
}

__device__ __forceinline__ void ffma2(u64& d, u64 a, u64 b) {
    asm("fma.rn.f32x2 %0, %1, %2, %0;" : "+l"(d) : "l"(a), "l"(b));
}

// C = A @ B, 64x64x64 fp32 in shared memory. 128 threads, each thread
// computes a 4x8 output tile using f32x2 packed FMA (16 FFMA2 per k).
__device__ __forceinline__ void mm64(float* __restrict__ C,
                                     const float* __restrict__ A,
                                     const float* __restrict__ B,
                                     int tid)
{
    const int tx = (tid & 7) * 8;    // output column base (8 cols = 4 f32x2)
    const int ty = (tid >> 3) * 4;   // output row base    (4 rows)

    u64 acc[4][4];
#pragma unroll
    for (int r = 0; r < 4; r++)
#pragma unroll
        for (int c = 0; c < 4; c++) acc[r][c] = 0ULL;

#pragma unroll 2
    for (int k0 = 0; k0 < 64; k0 += 4) {
        float a[4][4];
#pragma unroll
        for (int r = 0; r < 4; r++)
            *reinterpret_cast<float4*>(a[r]) =
                *reinterpret_cast<const float4*>(A + (ty + r) * LDM + k0);

#pragma unroll
        for (int ki = 0; ki < 4; ki++) {
            const float* brow = B + (k0 + ki) * LDM + tx;
            const ulonglong2 bl = *reinterpret_cast<const ulonglong2*>(brow);
            const ulonglong2 bh = *reinterpret_cast<const ulonglong2*>(brow + 4);
            const u64 b0 = bl.x, b1 = bl.y, b2 = bh.x, b3 = bh.y;
#pragma unroll
            for (int r = 0; r < 4; r++) {
                const u64 av = rep2(a[r][ki]);
                ffma2(acc[r][0], av, b0);
                ffma2(acc[r][1], av, b1);
                ffma2(acc[r][2], av, b2);
                ffma2(acc[r][3], av, b3);
            }
        }
    }

#pragma unroll
    for (int r = 0; r < 4; r++) {
        float* crow = C + (ty + r) * LDM + tx;
        *reinterpret_cast<ulonglong2*>(crow)     = make_ulonglong2(acc[r][0], acc[r][1]);
        *reinterpret_cast<ulonglong2*>(crow + 4) = make_ulonglong2(acc[r][2], acc[r][3]);
    }
}

// dst = I + (x*x)/64
__device__ __forceinline__ void build_m(float* __restrict__ dst,
                                        const float* __restrict__ xs, int tid)
{
    for (int e = tid; e < 4096; e += NTH) {
        const int i = e >> 6, j = e & 63;
        const float v = xs[i * LDM + j];
        dst[i * LDM + j] = v * v * (1.0f / 64.0f) + ((i == j) ? 1.0f : 0.0f);
    }
}

__global__ __launch_bounds__(NTH, 2)
void ppb_kernel(const float* __restrict__ adj, float* __restrict__ out)
{
    extern __shared__ float sm[];
    float* xs = sm;                 // current x
    float* sc = xs + MATF;          // scores = threshold(adj, 0.5)
    float* w0 = sc + MATF;          // work buffers
    float* w1 = w0 + MATF;
    float* w2 = w1 + MATF;
    float* w3 = w2 + MATF;
    float* red = w3 + MATF;         // [0..3] warp partials, [4] alpha

    const int tid = threadIdx.x;
    const int bidx = blockIdx.x;
    const float4* Ain4 = reinterpret_cast<const float4*>(adj + (size_t)bidx * 4096);

    // Load adj -> xs, compute scores (float4 granularity).
    for (int e4 = tid; e4 < 1024; e4 += NTH) {
        const float4 v = Ain4[e4];
        const int e = e4 * 4;
        const int i = e >> 6, j = e & 63;
        float* xp = xs + i * LDM + j;
        float* sp = sc + i * LDM + j;
        xp[0] = v.x; xp[1] = v.y; xp[2] = v.z; xp[3] = v.w;
        sp[0] = (v.x > 0.5f) ? v.x : 0.0f;
        sp[1] = (v.y > 0.5f) ? v.y : 0.0f;
        sp[2] = (v.z > 0.5f) ? v.z : 0.0f;
        sp[3] = (v.w > 0.5f) ? v.w : 0.0f;
    }
    if (tid == 0) red[4] = 0.0f;
    __syncthreads();

    const float INV64  = 1.0f / 64.0f;
    const float SHRINK = 0.002f * 0.01f;

#pragma unroll 1
    for (int it = 0; it < 50; it++) {
        const float alpha = red[4];
        const bool need_poly = (alpha != 0.0f);   // iter 0: grad poly term is exactly 0

        if (need_poly) {
            // poly = (I + x*x/64)^63 via addition chain 1,2,3,6,12,24,48,60,63 (8 matmuls)
            build_m(w0, xs, tid);     __syncthreads();
            mm64(w1, w0, w0, tid);    __syncthreads();   // m^2
            mm64(w2, w1, w0, tid);    __syncthreads();   // m^3  = m^2 @ m
            mm64(w0, w2, w2, tid);    __syncthreads();   // m^6  (m, m^2 dead)
            mm64(w1, w0, w0, tid);    __syncthreads();   // m^12
            mm64(w3, w1, w1, tid);    __syncthreads();   // m^24
            mm64(w0, w3, w3, tid);    __syncthreads();   // m^48 (m^6 dead)
            mm64(w3, w0, w1, tid);    __syncthreads();   // m^60 = m^48 @ m^12
            mm64(w1, w3, w2, tid);    __syncthreads();   // m^63 = m^60 @ m^3  -> poly in w1
        }

        // x update: grad = -scores + 2*alpha*x*poly^T/64 ; soft-threshold; clamp <= 1.
        for (int e = tid; e < 4096; e += NTH) {
            const int i = e >> 6, j = e & 63;
            float x = xs[i * LDM + j];
            float g = -sc[i * LDM + j];
            if (need_poly)
                g += ((2.0f * alpha) * x) * w1[j * LDM + i] * INV64;
            const float til = x - 0.01f * g;
            float nx = fabsf(til) - SHRINK;
            nx = fmaxf(nx, 0.0f);
            x = 1.0f - fmaxf(1.0f - nx, 0.0f);
            xs[i * LDM + j] = x;
        }
        __syncthreads();

        // h = trace((I + x*x/64)^30)/64 - 1, chain m2,m4,m6,m8,m14,m16 + trace-dot.
        build_m(w0, xs, tid);     __syncthreads();
        mm64(w1, w0, w0, tid);    __syncthreads();   // m^2
        mm64(w2, w1, w1, tid);    __syncthreads();   // m^4
        mm64(w3, w1, w2, tid);    __syncthreads();   // m^6  = m^2 @ m^4
        mm64(w0, w2, w2, tid);    __syncthreads();   // m^8  (m dead)
        mm64(w1, w3, w0, tid);    __syncthreads();   // m^14 = m^6 @ m^8
        mm64(w2, w0, w0, tid);    __syncthreads();   // m^16 = m^8 @ m^8

        // trace(m^30) = sum_{i,k} m14[i,k] * m16[k,i]
        float part = 0.0f;
        for (int e = tid; e < 4096; e += NTH) {
            const int i = e >> 6, k = e & 63;
            part += w1[i * LDM + k] * w2[k * LDM + i];
        }
#pragma unroll
        for (int off = 16; off > 0; off >>= 1)
            part += __shfl_xor_sync(0xFFFFFFFFu, part, off);
        if ((tid & 31) == 0) red[tid >> 5] = part;
        __syncthreads();
        if (tid == 0) {
            const float t = (red[0] + red[1]) + (red[2] + red[3]);
            red[4] += 0.01f * (t * INV64 - 1.0f);
        }
        __syncthreads();
    }

    // output = threshold(x, 0.5)
    float4* Out4 = reinterpret_cast<float4*>(out + (size_t)bidx * 4096);
    for (int e4 = tid; e4 < 1024; e4 += NTH) {
        const int e = e4 * 4;
        const int i = e >> 6, j = e & 63;
        const float* xp = xs + i * LDM + j;
        float4 v;
        v.x = (xp[0] > 0.5f) ? xp[0] : 0.0f;
        v.y = (xp[1] > 0.5f) ? xp[1] : 0.0f;
        v.z = (xp[2] > 0.5f) ? xp[2] : 0.0f;
        v.w = (xp[3] > 0.5f) ? xp[3] : 0.0f;
        Out4[e4] = v;
    }
}

extern "C" void kernel_launch(void* const* d_in, const int* in_sizes, int n_in,
                              void* d_out, int out_size)
{
    const float* adj = (const float*)d_in[0];
    float* out = (float*)d_out;

    const int batches = in_sizes[0] >> 12;
    const size_t smem = (size_t)(6 * MATF + 8) * sizeof(float);

    cudaFuncSetAttribute(ppb_kernel, cudaFuncAttributeMaxDynamicSharedMemorySize, (int)smem);
    ppb_kernel<<<batches, NTH, smem>>>(adj, out);
}

// round 3
// speedup vs baseline: 1.5055x; 1.5055x over previous
#include <cuda_runtime.h>

// PostProcessingBlock: 50 NOTEARS-style iterations on 512 independent 64x64
// matrices. One CTA (256 threads) per batch element, 3 CTAs/SM.
// State in shared memory (x + 3 work buffers); scores held in registers.
// Matmuls: packed fp32x2 FFMA, 4x4 output tile per thread.

#define LDM   68                  // padded row stride (floats)
#define MATF  (64 * LDM)
#define NTH   256

typedef unsigned long long u64;

__device__ __forceinline__ u64 rep2(float v) {
    u64 r;
    asm("mov.b64 %0, {%1, %1};" : "=l"(r) : "r"(__float_as_uint(v)));
    return r;
}
__device__ __forceinline__ void ffma2(u64& d, u64 a, u64 b) {
    asm("fma.rn.f32x2 %0, %1, %2, %0;" : "+l"(d) : "l"(a), "l"(b));
}

// C = A @ B, 64x64x64 fp32 in shared memory, 256 threads, 4x4 tile/thread.
// Per k: 8 FFMA2. Per 4k: 4 A-loads (LDS.128, warp-broadcast) + 4 B-loads.
__device__ __forceinline__ void mm64(float* __restrict__ C,
                                     const float* __restrict__ A,
                                     const float* __restrict__ B,
                                     int tx, int ty)
{
    u64 acc[4][2];
#pragma unroll
    for (int r = 0; r < 4; r++) { acc[r][0] = 0ULL; acc[r][1] = 0ULL; }

#pragma unroll 4
    for (int k0 = 0; k0 < 64; k0 += 4) {
        float a0[4], a1[4], a2[4], a3[4];
        *reinterpret_cast<float4*>(a0) = *reinterpret_cast<const float4*>(A + (ty + 0) * LDM + k0);
        *reinterpret_cast<float4*>(a1) = *reinterpret_cast<const float4*>(A + (ty + 1) * LDM + k0);
        *reinterpret_cast<float4*>(a2) = *reinterpret_cast<const float4*>(A + (ty + 2) * LDM + k0);
        *reinterpret_cast<float4*>(a3) = *reinterpret_cast<const float4*>(A + (ty + 3) * LDM + k0);

#pragma unroll
        for (int ki = 0; ki < 4; ki++) {
            const ulonglong2 b = *reinterpret_cast<const ulonglong2*>(B + (k0 + ki) * LDM + tx);
            ffma2(acc[0][0], rep2(a0[ki]), b.x);
            ffma2(acc[0][1], rep2(a0[ki]), b.y);
            ffma2(acc[1][0], rep2(a1[ki]), b.x);
            ffma2(acc[1][1], rep2(a1[ki]), b.y);
            ffma2(acc[2][0], rep2(a2[ki]), b.x);
            ffma2(acc[2][1], rep2(a2[ki]), b.y);
            ffma2(acc[3][0], rep2(a3[ki]), b.x);
            ffma2(acc[3][1], rep2(a3[ki]), b.y);
        }
    }

#pragma unroll
    for (int r = 0; r < 4; r++)
        *reinterpret_cast<ulonglong2*>(C + (ty + r) * LDM + tx) =
            make_ulonglong2(acc[r][0], acc[r][1]);
}

// dst = I + (x*x)/64
__device__ __forceinline__ void build_m(float* __restrict__ dst,
                                        const float* __restrict__ xs, int tid)
{
#pragma unroll
    for (int s = 0; s < 16; s++) {
        const int e = tid + s * NTH;
        const int i = e >> 6, j = e & 63;
        const float v = xs[i * LDM + j];
        dst[i * LDM + j] = v * v * (1.0f / 64.0f) + ((i == j) ? 1.0f : 0.0f);
    }
}

__global__ __launch_bounds__(NTH, 3)
void ppb_kernel(const float* __restrict__ adj, float* __restrict__ out)
{
    extern __shared__ float sm[];
    float* xs = sm;                 // current x
    float* w0 = xs + MATF;          // work buffers (3)
    float* w1 = w0 + MATF;
    float* w2 = w1 + MATF;
    float* red = w2 + MATF;         // [0..7] warp partials, [8] alpha

    const int tid = threadIdx.x;
    const int tx = (tid & 15) * 4;
    const int ty = (tid >> 4) * 4;
    const int bidx = blockIdx.x;
    const float4* Ain4 = reinterpret_cast<const float4*>(adj + (size_t)bidx * 4096);

    // Load adj -> xs; keep scores = threshold(adj,0.5) in registers
    // (layout matches the x-update loop: chunk s covers element4 tid + s*NTH).
    float scf[16];
#pragma unroll
    for (int s = 0; s < 4; s++) {
        const int e4 = tid + s * NTH;         // 0..1023
        const float4 v = Ain4[e4];
        const int i = e4 >> 4, j = (e4 & 15) * 4;
        float* xp = xs + i * LDM + j;
        xp[0] = v.x; xp[1] = v.y; xp[2] = v.z; xp[3] = v.w;
        scf[s * 4 + 0] = (v.x > 0.5f) ? v.x : 0.0f;
        scf[s * 4 + 1] = (v.y > 0.5f) ? v.y : 0.0f;
        scf[s * 4 + 2] = (v.z > 0.5f) ? v.z : 0.0f;
        scf[s * 4 + 3] = (v.w > 0.5f) ? v.w : 0.0f;
    }
    if (tid == 0) red[8] = 0.0f;
    __syncthreads();

    const float INV64  = 1.0f / 64.0f;
    const float SHRINK = 0.002f * 0.01f;

#pragma unroll 1
    for (int it = 0; it < 50; it++) {
        const float alpha = red[8];
        const bool need_poly = (alpha != 0.0f);   // iter 0: poly term exactly 0

        if (need_poly) {
            // poly = (I+x*x/64)^63, chain 1,2,3,6,12,15,30,60,63 (8 matmuls, 3 bufs)
            build_m(w0, xs, tid);       __syncthreads();
            mm64(w1, w0, w0, tx, ty);   __syncthreads();   // m^2
            mm64(w2, w1, w0, tx, ty);   __syncthreads();   // m^3
            mm64(w0, w2, w2, tx, ty);   __syncthreads();   // m^6
            mm64(w1, w0, w0, tx, ty);   __syncthreads();   // m^12
            mm64(w0, w1, w2, tx, ty);   __syncthreads();   // m^15 = m^12 @ m^3
            mm64(w1, w0, w0, tx, ty);   __syncthreads();   // m^30
            mm64(w0, w1, w1, tx, ty);   __syncthreads();   // m^60
            mm64(w1, w0, w2, tx, ty);   __syncthreads();   // m^63 -> w1
        }

        // x update: grad = -scores + 2*alpha*x*poly^T/64; soft-threshold; clamp <=1
        const float a2s = 2.0f * alpha * INV64;
#pragma unroll
        for (int s = 0; s < 4; s++) {
            const int e4 = tid + s * NTH;
            const int i = e4 >> 4, j = (e4 & 15) * 4;
            float* xp = xs + i * LDM + j;
#pragma unroll
            for (int c = 0; c < 4; c++) {
                float x = xp[c];
                float g = -scf[s * 4 + c];
                if (need_poly)
                    g += (a2s * x) * w1[(j + c) * LDM + i];
                const float til = x - 0.01f * g;
                float nx = fabsf(til) - SHRINK;
                nx = fmaxf(nx, 0.0f);
                xp[c] = 1.0f - fmaxf(1.0f - nx, 0.0f);
            }
        }
        __syncthreads();

        // h = trace((I+x*x/64)^30)/64 - 1;  trace(m^30) = dot(m^15, m^15^T)
        build_m(w0, xs, tid);       __syncthreads();
        mm64(w1, w0, w0, tx, ty);   __syncthreads();   // m^2
        mm64(w2, w1, w0, tx, ty);   __syncthreads();   // m^3
        mm64(w0, w2, w2, tx, ty);   __syncthreads();   // m^6
        mm64(w1, w0, w0, tx, ty);   __syncthreads();   // m^12
        mm64(w0, w1, w2, tx, ty);   __syncthreads();   // m^15

        float part = 0.0f;
#pragma unroll
        for (int s = 0; s < 16; s++) {
            const int e = tid + s * NTH;
            const int i = e >> 6, k = e & 63;
            part += w0[i * LDM + k] * w0[k * LDM + i];
        }
#pragma unroll
        for (int off = 16; off > 0; off >>= 1)
            part += __shfl_xor_sync(0xFFFFFFFFu, part, off);
        if ((tid & 31) == 0) red[tid >> 5] = part;
        __syncthreads();
        if (tid == 0) {
            float t = 0.0f;
#pragma unroll
            for (int w = 0; w < 8; w++) t += red[w];
            red[8] += 0.01f * (t * INV64 - 1.0f);
        }
        __syncthreads();
    }

    // output = threshold(x, 0.5)
    float4* Out4 = reinterpret_cast<float4*>(out + (size_t)bidx * 4096);
#pragma unroll
    for (int s = 0; s < 4; s++) {
        const int e4 = tid + s * NTH;
        const int i = e4 >> 4, j = (e4 & 15) * 4;
        const float* xp = xs + i * LDM + j;
        float4 v;
        v.x = (xp[0] > 0.5f) ? xp[0] : 0.0f;
        v.y = (xp[1] > 0.5f) ? xp[1] : 0.0f;
        v.z = (xp[2] > 0.5f) ? xp[2] : 0.0f;
        v.w = (xp[3] > 0.5f) ? xp[3] : 0.0f;
        Out4[e4] = v;
    }
}

extern "C" void kernel_launch(void* const* d_in, const int* in_sizes, int n_in,
                              void* d_out, int out_size)
{
    const float* adj = (const float*)d_in[0];
    float* out = (float*)d_out;

    const int batches = in_sizes[0] >> 12;
    const size_t smem = (size_t)(4 * MATF + 16) * sizeof(float);

    cudaFuncSetAttribute(ppb_kernel, cudaFuncAttributeMaxDynamicSharedMemorySize, (int)smem);
    ppb_kernel<<<batches, NTH, smem>>>(adj, out);
}